// round 15
// baseline (speedup 1.0000x reference)
#include <cuda_runtime.h>
#include <cuda_bf16.h>
#include <math.h>
#include <stdint.h>

// Problem constants
#define B_    256
#define V_    32000
#define S_    200
#define DECH  512
#define ENCD  1024
#define COMB  2048
#define RNNIN 1536
#define G3    1536   // 3*DECH

// ---------------- scratch (device globals; no allocation allowed) ----------
__device__ float g_q[B_ * ENCD];
__device__ float g_x[B_ * RNNIN];
__device__ float g_comb[B_ * COMB];
__device__ float g_gi[B_ * G3];
__device__ float g_gh[B_ * G3];
__device__ float g_logits[(size_t)B_ * V_];
__device__ float g_pg[B_];

// ======================= helpers =============================================
__device__ __forceinline__ uint32_t smem_u32(const void* p) {
    uint32_t a;
    asm("{ .reg .u64 t; cvta.to.shared.u64 t, %1; cvt.u32.u64 %0, t; }" : "=r"(a) : "l"(p));
    return a;
}

__device__ __forceinline__ uint32_t pack_bf16x2_rn(float f0, float f1) {
    uint32_t r;  // result = {lo: f0, hi: f1}
    asm("cvt.rn.satfinite.bf16x2.f32 %0, %1, %2;" : "=r"(r) : "f"(f1), "f"(f0));
    return r;
}

__device__ __forceinline__ void ldm_x4(uint32_t* r, uint32_t addr) {
    asm volatile("ldmatrix.sync.aligned.m8n8.x4.shared.b16 {%0,%1,%2,%3}, [%4];"
                 : "=r"(r[0]), "=r"(r[1]), "=r"(r[2]), "=r"(r[3]) : "r"(addr));
}

__device__ __forceinline__ void mma16816(float* c, const uint32_t* a, const uint32_t* b) {
    asm volatile(
        "mma.sync.aligned.m16n8k16.row.col.f32.bf16.bf16.f32 "
        "{%0,%1,%2,%3}, {%4,%5,%6,%7}, {%8,%9}, {%0,%1,%2,%3};"
        : "+f"(c[0]), "+f"(c[1]), "+f"(c[2]), "+f"(c[3])
        : "r"(a[0]), "r"(a[1]), "r"(a[2]), "r"(a[3]), "r"(b[0]), "r"(b[1]));
}

// fp32x4 -> bf16 hi (truncated) + lo (exact residual, rounded)
__device__ __forceinline__ void split4(float4 v, uint2& hi, uint2& lo) {
    uint32_t ux = __float_as_uint(v.x), uy = __float_as_uint(v.y);
    uint32_t uz = __float_as_uint(v.z), uw = __float_as_uint(v.w);
    hi.x = __byte_perm(ux, uy, 0x7632);
    hi.y = __byte_perm(uz, uw, 0x7632);
    lo.x = pack_bf16x2_rn(v.x - __uint_as_float(ux & 0xffff0000u),
                          v.y - __uint_as_float(uy & 0xffff0000u));
    lo.y = pack_bf16x2_rn(v.z - __uint_as_float(uz & 0xffff0000u),
                          v.w - __uint_as_float(uw & 0xffff0000u));
}

// 8 floats (two float4) -> one uint4 hi + one uint4 lo
__device__ __forceinline__ void split8(float4 v0, float4 v1, uint4& hi, uint4& lo) {
    uint2 h0, l0, h1, l1;
    split4(v0, h0, l0);
    split4(v1, h1, l1);
    hi = make_uint4(h0.x, h0.y, h1.x, h1.y);
    lo = make_uint4(l0.x, l0.y, l1.x, l1.y);
}

// =============== mma.sync GEMM: C = A * B^T (+bias) ==========================
// Loader geometry: 8-float segments (2x LDG.128 in, 2x STS.128 out) to halve
// STS issue count on the LSU (fc is LSU-issue bound).
#define FBM 64
#define FBK 32
#define FSA 40
#define FSB 40
#define FAB (FBM * FSA * 2)          // 5120 B

template<int KD, int NWT, int DEPTH>
__global__ void __launch_bounds__(256, 2)
gemm_mma(const float* __restrict__ A, const float* __restrict__ Bw,
         const float* __restrict__ bias, float* __restrict__ C, int Nld)
{
    constexpr int BN     = NWT * 32;
    constexpr int FBB    = BN * FSB * 2;
    constexpr int FSTAGE = 2 * FAB + 2 * FBB;
    constexpr int ITERS  = KD / FBK;
    constexpr int NJ     = NWT / 2;
    constexpr int NSEG   = NWT / 2;          // B 8-float segments per thread

    extern __shared__ char sm[];
    const int tid  = threadIdx.x;
    const int lane = tid & 31;
    const int wid  = tid >> 5;
    const int wm   = wid >> 2;
    const int wn   = wid & 3;
    const int m0 = blockIdx.x * FBM;
    const int n0 = blockIdx.y * BN;

    // A: 64 rows x 4 segs = 256 segs (1/thread); B: BN rows x 4 segs.
    const int arow = tid >> 2;
    const int acol = (tid & 3) * 8;
    int brow[NSEG], bcol[NSEG];
#pragma unroll
    for (int i = 0; i < NSEG; i++) {
        int seg = tid + 256 * i;
        brow[i] = seg >> 2;
        bcol[i] = (seg & 3) * 8;
    }

    float acc[2][NWT][4];
#pragma unroll
    for (int mi = 0; mi < 2; mi++)
#pragma unroll
        for (int na = 0; na < NWT; na++)
#pragma unroll
            for (int q = 0; q < 4; q++) acc[mi][na][q] = 0.f;

    const uint32_t smb = smem_u32(sm);

    auto g_load = [&](float4* av, float4* bv, int k0) {
        const float* ap = A + (size_t)(m0 + arow) * KD + k0 + acol;
        av[0] = *(const float4*)(ap);
        av[1] = *(const float4*)(ap + 4);
#pragma unroll
        for (int i = 0; i < NSEG; i++) {
            const float* bp = Bw + (size_t)(n0 + brow[i]) * KD + k0 + bcol[i];
            bv[2 * i]     = *(const float4*)(bp);
            bv[2 * i + 1] = *(const float4*)(bp + 4);
        }
    };
    auto s_store = [&](int s, const float4* av, const float4* bv) {
        char* st   = sm + s * FSTAGE;
        char* a_hi = st;
        char* a_lo = st + FAB;
        char* b_hi = st + 2 * FAB;
        char* b_lo = st + 2 * FAB + FBB;
        {
            uint4 hi, lo;
            split8(av[0], av[1], hi, lo);
            const int off = (arow * FSA + acol) * 2;
            *(uint4*)(a_hi + off) = hi;
            *(uint4*)(a_lo + off) = lo;
        }
#pragma unroll
        for (int i = 0; i < NSEG; i++) {
            uint4 hi, lo;
            split8(bv[2 * i], bv[2 * i + 1], hi, lo);
            const int off = (brow[i] * FSB + bcol[i]) * 2;
            *(uint4*)(b_hi + off) = hi;
            *(uint4*)(b_lo + off) = lo;
        }
    };

    uint32_t a_off[2][2], b_off[NJ][2];
#pragma unroll
    for (int ks = 0; ks < 2; ks++) {
#pragma unroll
        for (int mi = 0; mi < 2; mi++) {
            int row = wm * 32 + mi * 16 + (lane & 15);
            int col = ks * 16 + ((lane >> 4) << 3);
            a_off[mi][ks] = (uint32_t)(row * FSA + col) * 2;
        }
#pragma unroll
        for (int j = 0; j < NJ; j++) {
            int row = wn * (NWT * 8) + j * 16 + (((lane >> 4) & 1) << 3) + (lane & 7);
            int col = ks * 16 + (((lane >> 3) & 1) << 3);
            b_off[j][ks] = (uint32_t)(row * FSB + col) * 2;
        }
    }

    auto compute = [&](int s) {
        const uint32_t s_ahi = smb + s * FSTAGE;
        const uint32_t s_alo = s_ahi + FAB;
        const uint32_t s_bhi = s_ahi + 2 * FAB;
        const uint32_t s_blo = s_bhi + FBB;
#pragma unroll
        for (int ks = 0; ks < 2; ks++) {
            uint32_t ahi[2][4], alo[2][4], bhi[NJ][4], blo[NJ][4];
#pragma unroll
            for (int mi = 0; mi < 2; mi++) {
                ldm_x4(ahi[mi], s_ahi + a_off[mi][ks]);
                ldm_x4(alo[mi], s_alo + a_off[mi][ks]);
            }
#pragma unroll
            for (int j = 0; j < NJ; j++) {
                ldm_x4(bhi[j], s_bhi + b_off[j][ks]);
                ldm_x4(blo[j], s_blo + b_off[j][ks]);
            }
#pragma unroll
            for (int mi = 0; mi < 2; mi++)
#pragma unroll
                for (int na = 0; na < NWT; na++) {
                    const uint32_t* bh = &bhi[na >> 1][(na & 1) * 2];
                    const uint32_t* bl = &blo[na >> 1][(na & 1) * 2];
                    mma16816(acc[mi][na], ahi[mi], bh);
                    mma16816(acc[mi][na], ahi[mi], bl);
                    mma16816(acc[mi][na], alo[mi], bh);
                }
        }
    };

    if (DEPTH == 1) {
        float4 av[2], bv[2 * NSEG];
        g_load(av, bv, 0);
        s_store(0, av, bv);
        __syncthreads();
#pragma unroll 1
        for (int kc = 0; kc < ITERS; ++kc) {
            const int cur = kc & 1;
            if (kc + 1 < ITERS) g_load(av, bv, (kc + 1) * FBK);
            compute(cur);
            if (kc + 1 < ITERS) s_store(cur ^ 1, av, bv);
            __syncthreads();
        }
    } else {
        float4 a0[2], b0[2 * NSEG], a1[2], b1[2 * NSEG];
        g_load(a0, b0, 0);
        s_store(0, a0, b0);
        if (ITERS > 1) g_load(a1, b1, FBK);
        __syncthreads();
#pragma unroll 1
        for (int kc = 0; kc < ITERS; kc += 2) {
            if (kc + 2 < ITERS) g_load(a0, b0, (kc + 2) * FBK);
            compute(0);
            if (kc + 1 < ITERS) s_store(1, a1, b1);
            __syncthreads();
            if (kc + 1 < ITERS) {
                if (kc + 3 < ITERS) g_load(a1, b1, (kc + 3) * FBK);
                compute(1);
                if (kc + 2 < ITERS) s_store(0, a0, b0);
                __syncthreads();
            }
        }
    }

    // epilogue
    const int g  = lane >> 2;
    const int tg = lane & 3;
#pragma unroll
    for (int mi = 0; mi < 2; mi++) {
#pragma unroll
        for (int na = 0; na < NWT; na++) {
            const int col = n0 + wn * (NWT * 8) + na * 8 + tg * 2;
            const int r0 = m0 + wm * 32 + mi * 16 + g;
            const float bz0 = bias ? __ldg(&bias[col])     : 0.f;
            const float bz1 = bias ? __ldg(&bias[col + 1]) : 0.f;
            float2 v0, v1;
            v0.x = acc[mi][na][0] + bz0;
            v0.y = acc[mi][na][1] + bz1;
            v1.x = acc[mi][na][2] + bz0;
            v1.y = acc[mi][na][3] + bz1;
            *(float2*)&C[(size_t)r0 * Nld + col]       = v0;
            *(float2*)&C[(size_t)(r0 + 8) * Nld + col] = v1;
        }
    }
}

// =============== fused q + gh GEMM: dh @ {W_attn,w_hh}^T =====================
__global__ void __launch_bounds__(256, 2)
qgh_gemm(const float* __restrict__ A,
         const float* __restrict__ B1, const float* __restrict__ B2,
         float* __restrict__ C1, float* __restrict__ C2)
{
    constexpr int KD     = 512;
    constexpr int NWT    = 2;
    constexpr int BN     = 64;
    constexpr int FBB    = BN * FSB * 2;
    constexpr int FSTAGE = 2 * FAB + 2 * FBB;
    constexpr int ITERS  = KD / FBK;       // 16
    constexpr int NJ     = 1;
    constexpr int NSEG   = 1;

    extern __shared__ char sm[];
    const int tid  = threadIdx.x;
    const int lane = tid & 31;
    const int wid  = tid >> 5;
    const int wm   = wid >> 2;
    const int wn   = wid & 3;
    const int m0 = blockIdx.x * FBM;
    const int n0g = blockIdx.y * BN;

    const bool first = (n0g < ENCD);
    const float* Bw = first ? B1 : B2;
    float* C        = first ? C1 : C2;
    const int Nld   = first ? ENCD : G3;
    const int n0    = first ? n0g : (n0g - ENCD);

    const int arow = tid >> 2;
    const int acol = (tid & 3) * 8;
    const int brow0 = tid >> 2;
    const int bcol0 = (tid & 3) * 8;

    float acc[2][NWT][4];
#pragma unroll
    for (int mi = 0; mi < 2; mi++)
#pragma unroll
        for (int na = 0; na < NWT; na++)
#pragma unroll
            for (int q = 0; q < 4; q++) acc[mi][na][q] = 0.f;

    const uint32_t smb = smem_u32(sm);

    auto g_load = [&](float4* av, float4* bv, int k0) {
        const float* ap = A + (size_t)(m0 + arow) * KD + k0 + acol;
        av[0] = *(const float4*)(ap);
        av[1] = *(const float4*)(ap + 4);
        const float* bp = Bw + (size_t)(n0 + brow0) * KD + k0 + bcol0;
        bv[0] = *(const float4*)(bp);
        bv[1] = *(const float4*)(bp + 4);
    };
    auto s_store = [&](int s, const float4* av, const float4* bv) {
        char* st   = sm + s * FSTAGE;
        char* a_hi = st;
        char* a_lo = st + FAB;
        char* b_hi = st + 2 * FAB;
        char* b_lo = st + 2 * FAB + FBB;
        {
            uint4 hi, lo;
            split8(av[0], av[1], hi, lo);
            const int off = (arow * FSA + acol) * 2;
            *(uint4*)(a_hi + off) = hi;
            *(uint4*)(a_lo + off) = lo;
        }
        {
            uint4 hi, lo;
            split8(bv[0], bv[1], hi, lo);
            const int off = (brow0 * FSB + bcol0) * 2;
            *(uint4*)(b_hi + off) = hi;
            *(uint4*)(b_lo + off) = lo;
        }
    };

    uint32_t a_off[2][2], b_off[NJ][2];
#pragma unroll
    for (int ks = 0; ks < 2; ks++) {
#pragma unroll
        for (int mi = 0; mi < 2; mi++) {
            int row = wm * 32 + mi * 16 + (lane & 15);
            int col = ks * 16 + ((lane >> 4) << 3);
            a_off[mi][ks] = (uint32_t)(row * FSA + col) * 2;
        }
#pragma unroll
        for (int j = 0; j < NJ; j++) {
            int row = wn * (NWT * 8) + j * 16 + (((lane >> 4) & 1) << 3) + (lane & 7);
            int col = ks * 16 + (((lane >> 3) & 1) << 3);
            b_off[j][ks] = (uint32_t)(row * FSB + col) * 2;
        }
    }

    auto compute = [&](int s) {
        const uint32_t s_ahi = smb + s * FSTAGE;
        const uint32_t s_alo = s_ahi + FAB;
        const uint32_t s_bhi = s_ahi + 2 * FAB;
        const uint32_t s_blo = s_bhi + FBB;
#pragma unroll
        for (int ks = 0; ks < 2; ks++) {
            uint32_t ahi[2][4], alo[2][4], bhi[NJ][4], blo[NJ][4];
#pragma unroll
            for (int mi = 0; mi < 2; mi++) {
                ldm_x4(ahi[mi], s_ahi + a_off[mi][ks]);
                ldm_x4(alo[mi], s_alo + a_off[mi][ks]);
            }
#pragma unroll
            for (int j = 0; j < NJ; j++) {
                ldm_x4(bhi[j], s_bhi + b_off[j][ks]);
                ldm_x4(blo[j], s_blo + b_off[j][ks]);
            }
#pragma unroll
            for (int mi = 0; mi < 2; mi++)
#pragma unroll
                for (int na = 0; na < NWT; na++) {
                    const uint32_t* bh = &bhi[na >> 1][(na & 1) * 2];
                    const uint32_t* bl = &blo[na >> 1][(na & 1) * 2];
                    mma16816(acc[mi][na], ahi[mi], bh);
                    mma16816(acc[mi][na], ahi[mi], bl);
                    mma16816(acc[mi][na], alo[mi], bh);
                }
        }
    };

    float4 a0[2], b0[2], a1[2], b1[2];
    g_load(a0, b0, 0);
    s_store(0, a0, b0);
    g_load(a1, b1, FBK);
    __syncthreads();
#pragma unroll 1
    for (int kc = 0; kc < ITERS; kc += 2) {
        if (kc + 2 < ITERS) g_load(a0, b0, (kc + 2) * FBK);
        compute(0);
        if (kc + 1 < ITERS) s_store(1, a1, b1);
        __syncthreads();
        if (kc + 1 < ITERS) {
            if (kc + 3 < ITERS) g_load(a1, b1, (kc + 3) * FBK);
            compute(1);
            if (kc + 2 < ITERS) s_store(0, a0, b0);
            __syncthreads();
        }
    }

    const int g  = lane >> 2;
    const int tg = lane & 3;
#pragma unroll
    for (int mi = 0; mi < 2; mi++) {
#pragma unroll
        for (int na = 0; na < NWT; na++) {
            const int col = n0 + wn * (NWT * 8) + na * 8 + tg * 2;
            const int r0 = m0 + wm * 32 + mi * 16 + g;
            float2 v0, v1;
            v0.x = acc[mi][na][0];
            v0.y = acc[mi][na][1];
            v1.x = acc[mi][na][2];
            v1.y = acc[mi][na][3];
            *(float2*)&C[(size_t)r0 * Nld + col]       = v0;
            *(float2*)&C[(size_t)(r0 + 8) * Nld + col] = v1;
        }
    }
}

#define STAGE_OF(NWT) (2 * FAB + 2 * ((NWT) * 32 * FSB * 2))
#define SMEM_OF(NWT)  (2 * STAGE_OF(NWT))

// ---------------- embedding gather -----------------------------------------
__global__ void prep_kernel(const int* __restrict__ word,
                            const float* __restrict__ emb)
{
    const int b = blockIdx.x;
    const int t = threadIdx.x;                 // 512
    const float v = emb[(size_t)word[b] * 512 + t];
    g_x[b * RNNIN + t] = v;
    g_comb[b * COMB + RNNIN + t] = v;
}

// ------- flash attention, DOUBLE-BUFFERED tile: enc read once ---------------
#define ACH 8
#define ATT_SMEM ((ENCD + 2 * ACH * ENCD + S_ + 8) * 4)

__global__ void __launch_bounds__(256) attn_flash(
    const float* __restrict__ enc, const int* __restrict__ src,
    float* __restrict__ out_scores)
{
    extern __shared__ float asm_[];
    float* qs   = asm_;                       // [1024]
    float* tl   = asm_ + ENCD;                // [2][8][1024]
    float* satt = asm_ + ENCD + 2 * ACH * ENCD;  // [200]
    __shared__ float attc[2][ACH];

    const int b = blockIdx.x;
    const int tid = threadIdx.x;
    const int warp = tid >> 5, lane = tid & 31;

    for (int d = tid; d < ENCD; d += 256) qs[d] = g_q[b * ENCD + d];
    __syncthreads();

    const float* encb = enc + (size_t)b * S_ * ENCD;

    float4 r[8];
    auto ldchunk = [&](int s0) {
        const float* e = encb + (size_t)(s0 + warp) * ENCD;
#pragma unroll
        for (int i = 0; i < 8; i++)
            r[i] = *(const float4*)(e + (lane + 32 * i) * 4);
    };
    auto store_dot = [&](int buf, int s0) {
        float* trow = tl + (buf * ACH + warp) * ENCD;
        float acc = 0.f;
#pragma unroll
        for (int i = 0; i < 8; i++) {
            const int d4 = (lane + 32 * i) * 4;
            *(float4*)(trow + d4) = r[i];
            acc += r[i].x * qs[d4] + r[i].y * qs[d4 + 1]
                 + r[i].z * qs[d4 + 2] + r[i].w * qs[d4 + 3];
        }
#pragma unroll
        for (int o = 16; o; o >>= 1) acc += __shfl_xor_sync(~0u, acc, o);
        if (lane == 0) {
            const int s = s0 + warp;
            const float a = (src[b * S_ + s] == 0) ? -1000000.0f : acc;
            attc[buf][warp] = a;
            satt[s] = a;
        }
    };

    float m = -INFINITY, l = 0.f;
    float c0 = 0.f, c1 = 0.f, c2 = 0.f, c3 = 0.f;

    ldchunk(0);
    store_dot(0, 0);
    __syncthreads();

    constexpr int NCH = S_ / ACH;             // 25
#pragma unroll 1
    for (int c = 0; c < NCH; ++c) {
        const int cur = c & 1;
        if (c + 1 < NCH) ldchunk((c + 1) * ACH);
        const float* tb = tl + cur * ACH * ENCD;
#pragma unroll
        for (int rr = 0; rr < ACH; rr++) {
            const float a = attc[cur][rr];
            const float mn = fmaxf(m, a);
            const float scale = __expf(m - mn);
            const float f = __expf(a - mn);
            const float* tr = tb + rr * ENCD;
            c0 = c0 * scale + f * tr[tid];
            c1 = c1 * scale + f * tr[tid + 256];
            c2 = c2 * scale + f * tr[tid + 512];
            c3 = c3 * scale + f * tr[tid + 768];
            l = l * scale + f;
            m = mn;
        }
        if (c + 1 < NCH) store_dot(cur ^ 1, (c + 1) * ACH);
        __syncthreads();
    }

    const float inv = 1.f / l;
    c0 *= inv; c1 *= inv; c2 *= inv; c3 *= inv;
    const int d = tid;
    g_x[b * RNNIN + 512 + d]       = c0;   g_comb[b * COMB + 512 + d]       = c0;
    g_x[b * RNNIN + 512 + d + 256] = c1;   g_comb[b * COMB + 512 + d + 256] = c1;
    g_x[b * RNNIN + 512 + d + 512] = c2;   g_comb[b * COMB + 512 + d + 512] = c2;
    g_x[b * RNNIN + 512 + d + 768] = c3;   g_comb[b * COMB + 512 + d + 768] = c3;

    if (tid < S_) out_scores[b * S_ + tid] = __expf(satt[tid] - m) * inv;
}

// ---------------- GRU gates -------------------------------------------------
__global__ void gru_kernel(const float* __restrict__ h_prev,
                           const float* __restrict__ b_ih,
                           const float* __restrict__ b_hh,
                           float* __restrict__ out_hidden)
{
    const int b = blockIdx.x;
    const int t = threadIdx.x;                 // 512
    const float ir  = g_gi[b * G3 + t]         + b_ih[t];
    const float iz  = g_gi[b * G3 + 512 + t]   + b_ih[512 + t];
    const float in_ = g_gi[b * G3 + 1024 + t]  + b_ih[1024 + t];
    const float hr  = g_gh[b * G3 + t]         + b_hh[t];
    const float hz  = g_gh[b * G3 + 512 + t]   + b_hh[512 + t];
    const float hn  = g_gh[b * G3 + 1024 + t]  + b_hh[1024 + t];
    const float r = 1.f / (1.f + __expf(-(ir + hr)));
    const float z = 1.f / (1.f + __expf(-(iz + hz)));
    const float n = tanhf(in_ + r * hn);
    const float h = (1.f - z) * n + z * h_prev[b * DECH + t];
    out_hidden[b * DECH + t] = h;
    g_comb[b * COMB + t] = h;
}

// ---------------- pointer gate probability ---------------------------------
__global__ void __launch_bounds__(256) ptr_kernel(
    const float* __restrict__ ptr_w, const float* __restrict__ ptr_b)
{
    const int b = blockIdx.x;
    const int tid = threadIdx.x;
    float acc = 0.f;
    for (int k = tid; k < COMB; k += 256)
        acc = fmaf(g_comb[b * COMB + k], ptr_w[k], acc);
    __shared__ float red[8];
#pragma unroll
    for (int o = 16; o; o >>= 1) acc += __shfl_xor_sync(~0u, acc, o);
    if ((tid & 31) == 0) red[tid >> 5] = acc;
    __syncthreads();
    if (tid == 0) {
        float s = 0.f;
        for (int i = 0; i < 8; i++) s += red[i];
        g_pg[b] = 1.f / (1.f + __expf(-(s + ptr_b[0])));
    }
}

// --------- softmax over V (online) + scaling + fused pointer scatter --------
__global__ void __launch_bounds__(1024) softmax_kernel(
    float* __restrict__ out, const int* __restrict__ src,
    const float* __restrict__ scores)
{
    const int b = blockIdx.x;
    const int tid = threadIdx.x;
    const float* lg = g_logits + (size_t)b * V_;
    __shared__ float redm[32], reds[32];

    float m = -INFINITY, s = 0.f;
    for (int v = tid; v < V_; v += 1024) {
        const float x = lg[v];
        const float mo = m;
        m = fmaxf(m, x);
        s = s * __expf(mo - m) + __expf(x - m);
    }
#pragma unroll
    for (int o = 16; o; o >>= 1) {
        const float m2 = __shfl_xor_sync(~0u, m, o);
        const float s2 = __shfl_xor_sync(~0u, s, o);
        const float mn = fmaxf(m, m2);
        s = s * __expf(m - mn) + s2 * __expf(m2 - mn);
        m = mn;
    }
    if ((tid & 31) == 0) { redm[tid >> 5] = m; reds[tid >> 5] = s; }
    __syncthreads();
    if (tid < 32) {
        float mm = redm[tid], ss = reds[tid];
#pragma unroll
        for (int o = 16; o; o >>= 1) {
            const float m2 = __shfl_xor_sync(~0u, mm, o);
            const float s2 = __shfl_xor_sync(~0u, ss, o);
            const float mn = fmaxf(mm, m2);
            ss = ss * __expf(mm - mn) + s2 * __expf(m2 - mn);
            mm = mn;
        }
        if (tid == 0) { redm[0] = mm; reds[0] = ss; }
    }
    __syncthreads();
    m = redm[0];
    const float pg = g_pg[b];
    const float scale = pg / reds[0];
    for (int v = tid; v < V_; v += 1024)
        out[(size_t)b * V_ + v] = __expf(lg[v] - m) * scale;
    __syncthreads();
    if (tid < S_) {
        const int idx = src[b * S_ + tid];
        atomicAdd(&out[(size_t)b * V_ + idx], (1.f - pg) * scores[b * S_ + tid]);
    }
}

// ---------------- launch -----------------------------------------------------
extern "C" void kernel_launch(void* const* d_in, const int* in_sizes, int n_in,
                              void* d_out, int out_size)
{
    const int*   word    = (const int*)  d_in[0];
    const float* dh      = (const float*)d_in[1];
    const float* enc     = (const float*)d_in[2];
    const int*   src     = (const int*)  d_in[3];
    const float* emb     = (const float*)d_in[4];
    const float* W_attn  = (const float*)d_in[5];
    const float* w_ih    = (const float*)d_in[6];
    const float* w_hh    = (const float*)d_in[7];
    const float* b_ih    = (const float*)d_in[8];
    const float* b_hh    = (const float*)d_in[9];
    const float* fc_w    = (const float*)d_in[10];
    const float* fc_b    = (const float*)d_in[11];
    const float* ptr_w   = (const float*)d_in[12];
    const float* ptr_b   = (const float*)d_in[13];

    float* out        = (float*)d_out;
    float* out_probs  = out;                                 // (B,1,V)
    float* out_hidden = out + (size_t)B_ * V_;               // (B,DECH)
    float* out_scores = out_hidden + (size_t)B_ * DECH;      // (B,1,S)

    float *pq, *px, *pcomb, *pgi, *pgh, *plog;
    cudaGetSymbolAddress((void**)&pq,    g_q);
    cudaGetSymbolAddress((void**)&px,    g_x);
    cudaGetSymbolAddress((void**)&pcomb, g_comb);
    cudaGetSymbolAddress((void**)&pgi,   g_gi);
    cudaGetSymbolAddress((void**)&pgh,   g_gh);
    cudaGetSymbolAddress((void**)&plog,  g_logits);

    static bool attr_set = false;
    if (!attr_set) {
        cudaFuncSetAttribute((void*)gemm_mma<2048, 4, 1>,
            cudaFuncAttributeMaxDynamicSharedMemorySize, SMEM_OF(4));
        cudaFuncSetAttribute((void*)gemm_mma<1536, 2, 2>,
            cudaFuncAttributeMaxDynamicSharedMemorySize, SMEM_OF(2));
        cudaFuncSetAttribute((void*)qgh_gemm,
            cudaFuncAttributeMaxDynamicSharedMemorySize, SMEM_OF(2));
        cudaFuncSetAttribute((void*)attn_flash,
            cudaFuncAttributeMaxDynamicSharedMemorySize, ATT_SMEM);
        attr_set = true;
    }

    // 1) embedding gather into x and comb
    prep_kernel<<<B_, 512>>>(word, emb);
    // 2) q = dh @ W_attn^T AND gh = dh @ w_hh^T in ONE launch
    qgh_gemm<<<dim3(B_/FBM, (ENCD + G3)/64), 256, SMEM_OF(2)>>>(
        dh, W_attn, w_hh, pq, pgh);
    // 3) flash attention (double-buffered tile): scores + context
    attn_flash<<<B_, 256, ATT_SMEM>>>(enc, src, out_scores);
    // 4) gi = x @ w_ih^T
    gemm_mma<1536, 2, 2><<<dim3(B_/FBM, G3/64), 256, SMEM_OF(2)>>>(
        px, w_ih, nullptr, pgi, G3);
    // 5) GRU gates -> hidden
    gru_kernel<<<B_, 512>>>(dh, b_ih, b_hh, out_hidden);
    // 6) logits = comb @ fc_w^T + fc_b (NWT=4, DEPTH=1, STS.128 loader)
    gemm_mma<2048, 4, 1><<<dim3(B_/FBM, V_/128), 256, SMEM_OF(4)>>>(
        pcomb, fc_w, fc_b, plog, V_);
    // 7) prob_gen
    ptr_kernel<<<B_, 256>>>(ptr_w, ptr_b);
    // 8) out = prob_gen * softmax(logits) + fused pointer scatter
    softmax_kernel<<<B_, 1024>>>(out_probs, src, out_scores);
}

// round 16
// speedup vs baseline: 1.1464x; 1.1464x over previous
#include <cuda_runtime.h>
#include <cuda_bf16.h>
#include <math.h>
#include <stdint.h>

// Problem constants
#define B_    256
#define V_    32000
#define S_    200
#define DECH  512
#define ENCD  1024
#define COMB  2048
#define RNNIN 1536
#define G3    1536   // 3*DECH

// ---------------- scratch (device globals; no allocation allowed) ----------
__device__ float g_q[B_ * ENCD];
__device__ float g_x[B_ * RNNIN];
__device__ float g_comb[B_ * COMB];
__device__ float g_gi[B_ * G3];
__device__ float g_gh[B_ * G3];
__device__ float g_logits[(size_t)B_ * V_];

// ======================= helpers =============================================
__device__ __forceinline__ uint32_t smem_u32(const void* p) {
    uint32_t a;
    asm("{ .reg .u64 t; cvta.to.shared.u64 t, %1; cvt.u32.u64 %0, t; }" : "=r"(a) : "l"(p));
    return a;
}

__device__ __forceinline__ uint32_t pack_bf16x2_rn(float f0, float f1) {
    uint32_t r;  // result = {lo: f0, hi: f1}
    asm("cvt.rn.satfinite.bf16x2.f32 %0, %1, %2;" : "=r"(r) : "f"(f1), "f"(f0));
    return r;
}

__device__ __forceinline__ void ldm_x4(uint32_t* r, uint32_t addr) {
    asm volatile("ldmatrix.sync.aligned.m8n8.x4.shared.b16 {%0,%1,%2,%3}, [%4];"
                 : "=r"(r[0]), "=r"(r[1]), "=r"(r[2]), "=r"(r[3]) : "r"(addr));
}

__device__ __forceinline__ void mma16816(float* c, const uint32_t* a, const uint32_t* b) {
    asm volatile(
        "mma.sync.aligned.m16n8k16.row.col.f32.bf16.bf16.f32 "
        "{%0,%1,%2,%3}, {%4,%5,%6,%7}, {%8,%9}, {%0,%1,%2,%3};"
        : "+f"(c[0]), "+f"(c[1]), "+f"(c[2]), "+f"(c[3])
        : "r"(a[0]), "r"(a[1]), "r"(a[2]), "r"(a[3]), "r"(b[0]), "r"(b[1]));
}

// fp32x4 -> bf16 hi (truncated) + lo (exact residual, rounded)
__device__ __forceinline__ void split4(float4 v, uint2& hi, uint2& lo) {
    uint32_t ux = __float_as_uint(v.x), uy = __float_as_uint(v.y);
    uint32_t uz = __float_as_uint(v.z), uw = __float_as_uint(v.w);
    hi.x = __byte_perm(ux, uy, 0x7632);
    hi.y = __byte_perm(uz, uw, 0x7632);
    lo.x = pack_bf16x2_rn(v.x - __uint_as_float(ux & 0xffff0000u),
                          v.y - __uint_as_float(uy & 0xffff0000u));
    lo.y = pack_bf16x2_rn(v.z - __uint_as_float(uz & 0xffff0000u),
                          v.w - __uint_as_float(uw & 0xffff0000u));
}

// =============== mma.sync GEMM: C = A * B^T (+bias) ==========================
#define FBM 64
#define FBK 32
#define FSA 40
#define FSB 40
#define FAB (FBM * FSA * 2)          // 5120 B

template<int KD, int NWT, int DEPTH>
__global__ void __launch_bounds__(256, 2)
gemm_mma(const float* __restrict__ A, const float* __restrict__ Bw,
         const float* __restrict__ bias, float* __restrict__ C, int Nld)
{
    constexpr int BN     = NWT * 32;
    constexpr int FBB    = BN * FSB * 2;
    constexpr int FSTAGE = 2 * FAB + 2 * FBB;
    constexpr int ITERS  = KD / FBK;
    constexpr int NJ     = NWT / 2;

    extern __shared__ char sm[];
    const int tid  = threadIdx.x;
    const int lane = tid & 31;
    const int wid  = tid >> 5;
    const int wm   = wid >> 2;
    const int wn   = wid & 3;
    const int m0 = blockIdx.x * FBM;
    const int n0 = blockIdx.y * BN;

    int arow[2], acol[2], brow[NWT], bcol[NWT];
#pragma unroll
    for (int i = 0; i < 2; i++) {
        int idx = tid + 256 * i;
        arow[i] = idx >> 3;
        acol[i] = (idx & 7) * 4;
    }
#pragma unroll
    for (int i = 0; i < NWT; i++) {
        int idx = tid + 256 * i;
        brow[i] = idx >> 3;
        bcol[i] = (idx & 7) * 4;
    }

    float acc[2][NWT][4];
#pragma unroll
    for (int mi = 0; mi < 2; mi++)
#pragma unroll
        for (int na = 0; na < NWT; na++)
#pragma unroll
            for (int q = 0; q < 4; q++) acc[mi][na][q] = 0.f;

    const uint32_t smb = smem_u32(sm);

    auto g_load = [&](float4* av, float4* bv, int k0) {
#pragma unroll
        for (int i = 0; i < 2; i++)
            av[i] = *(const float4*)(A + (size_t)(m0 + arow[i]) * KD + k0 + acol[i]);
#pragma unroll
        for (int i = 0; i < NWT; i++)
            bv[i] = *(const float4*)(Bw + (size_t)(n0 + brow[i]) * KD + k0 + bcol[i]);
    };
    auto s_store = [&](int s, const float4* av, const float4* bv) {
        char* st   = sm + s * FSTAGE;
        char* a_hi = st;
        char* a_lo = st + FAB;
        char* b_hi = st + 2 * FAB;
        char* b_lo = st + 2 * FAB + FBB;
#pragma unroll
        for (int i = 0; i < 2; i++) {
            uint2 hi, lo;
            split4(av[i], hi, lo);
            const int off = (arow[i] * FSA + acol[i]) * 2;
            *(uint2*)(a_hi + off) = hi;
            *(uint2*)(a_lo + off) = lo;
        }
#pragma unroll
        for (int i = 0; i < NWT; i++) {
            uint2 hi, lo;
            split4(bv[i], hi, lo);
            const int off = (brow[i] * FSB + bcol[i]) * 2;
            *(uint2*)(b_hi + off) = hi;
            *(uint2*)(b_lo + off) = lo;
        }
    };

    uint32_t a_off[2][2], b_off[NJ][2];
#pragma unroll
    for (int ks = 0; ks < 2; ks++) {
#pragma unroll
        for (int mi = 0; mi < 2; mi++) {
            int row = wm * 32 + mi * 16 + (lane & 15);
            int col = ks * 16 + ((lane >> 4) << 3);
            a_off[mi][ks] = (uint32_t)(row * FSA + col) * 2;
        }
#pragma unroll
        for (int j = 0; j < NJ; j++) {
            int row = wn * (NWT * 8) + j * 16 + (((lane >> 4) & 1) << 3) + (lane & 7);
            int col = ks * 16 + (((lane >> 3) & 1) << 3);
            b_off[j][ks] = (uint32_t)(row * FSB + col) * 2;
        }
    }

    auto compute = [&](int s) {
        const uint32_t s_ahi = smb + s * FSTAGE;
        const uint32_t s_alo = s_ahi + FAB;
        const uint32_t s_bhi = s_ahi + 2 * FAB;
        const uint32_t s_blo = s_bhi + FBB;
#pragma unroll
        for (int ks = 0; ks < 2; ks++) {
            uint32_t ahi[2][4], alo[2][4], bhi[NJ][4], blo[NJ][4];
#pragma unroll
            for (int mi = 0; mi < 2; mi++) {
                ldm_x4(ahi[mi], s_ahi + a_off[mi][ks]);
                ldm_x4(alo[mi], s_alo + a_off[mi][ks]);
            }
#pragma unroll
            for (int j = 0; j < NJ; j++) {
                ldm_x4(bhi[j], s_bhi + b_off[j][ks]);
                ldm_x4(blo[j], s_blo + b_off[j][ks]);
            }
#pragma unroll
            for (int mi = 0; mi < 2; mi++)
#pragma unroll
                for (int na = 0; na < NWT; na++) {
                    const uint32_t* bh = &bhi[na >> 1][(na & 1) * 2];
                    const uint32_t* bl = &blo[na >> 1][(na & 1) * 2];
                    mma16816(acc[mi][na], ahi[mi], bh);
                    mma16816(acc[mi][na], ahi[mi], bl);
                    mma16816(acc[mi][na], alo[mi], bh);
                }
        }
    };

    if (DEPTH == 1) {
        float4 av[2], bv[NWT];
        g_load(av, bv, 0);
        s_store(0, av, bv);
        __syncthreads();
#pragma unroll 1
        for (int kc = 0; kc < ITERS; ++kc) {
            const int cur = kc & 1;
            if (kc + 1 < ITERS) g_load(av, bv, (kc + 1) * FBK);
            compute(cur);
            if (kc + 1 < ITERS) s_store(cur ^ 1, av, bv);
            __syncthreads();
        }
    } else {
        float4 a0[2], b0[NWT], a1[2], b1[NWT];
        g_load(a0, b0, 0);
        s_store(0, a0, b0);
        if (ITERS > 1) g_load(a1, b1, FBK);
        __syncthreads();
#pragma unroll 1
        for (int kc = 0; kc < ITERS; kc += 2) {
            if (kc + 2 < ITERS) g_load(a0, b0, (kc + 2) * FBK);
            compute(0);
            if (kc + 1 < ITERS) s_store(1, a1, b1);
            __syncthreads();
            if (kc + 1 < ITERS) {
                if (kc + 3 < ITERS) g_load(a1, b1, (kc + 3) * FBK);
                compute(1);
                if (kc + 2 < ITERS) s_store(0, a0, b0);
                __syncthreads();
            }
        }
    }

    // epilogue
    const int g  = lane >> 2;
    const int tg = lane & 3;
#pragma unroll
    for (int mi = 0; mi < 2; mi++) {
#pragma unroll
        for (int na = 0; na < NWT; na++) {
            const int col = n0 + wn * (NWT * 8) + na * 8 + tg * 2;
            const int r0 = m0 + wm * 32 + mi * 16 + g;
            const float bz0 = bias ? __ldg(&bias[col])     : 0.f;
            const float bz1 = bias ? __ldg(&bias[col + 1]) : 0.f;
            float2 v0, v1;
            v0.x = acc[mi][na][0] + bz0;
            v0.y = acc[mi][na][1] + bz1;
            v1.x = acc[mi][na][2] + bz0;
            v1.y = acc[mi][na][3] + bz1;
            *(float2*)&C[(size_t)r0 * Nld + col]       = v0;
            *(float2*)&C[(size_t)(r0 + 8) * Nld + col] = v1;
        }
    }
}

// =============== fused q + gh GEMM: dh @ {W_attn,w_hh}^T =====================
__global__ void __launch_bounds__(256, 2)
qgh_gemm(const float* __restrict__ A,
         const float* __restrict__ B1, const float* __restrict__ B2,
         float* __restrict__ C1, float* __restrict__ C2)
{
    constexpr int KD     = 512;
    constexpr int NWT    = 2;
    constexpr int BN     = 64;
    constexpr int FBB    = BN * FSB * 2;
    constexpr int FSTAGE = 2 * FAB + 2 * FBB;
    constexpr int ITERS  = KD / FBK;       // 16
    constexpr int NJ     = 1;

    extern __shared__ char sm[];
    const int tid  = threadIdx.x;
    const int lane = tid & 31;
    const int wid  = tid >> 5;
    const int wm   = wid >> 2;
    const int wn   = wid & 3;
    const int m0 = blockIdx.x * FBM;
    const int n0g = blockIdx.y * BN;

    const bool first = (n0g < ENCD);
    const float* Bw = first ? B1 : B2;
    float* C        = first ? C1 : C2;
    const int Nld   = first ? ENCD : G3;
    const int n0    = first ? n0g : (n0g - ENCD);

    int arow[2], acol[2], brow[NWT], bcol[NWT];
#pragma unroll
    for (int i = 0; i < 2; i++) {
        int idx = tid + 256 * i;
        arow[i] = idx >> 3;
        acol[i] = (idx & 7) * 4;
    }
#pragma unroll
    for (int i = 0; i < NWT; i++) {
        int idx = tid + 256 * i;
        brow[i] = idx >> 3;
        bcol[i] = (idx & 7) * 4;
    }

    float acc[2][NWT][4];
#pragma unroll
    for (int mi = 0; mi < 2; mi++)
#pragma unroll
        for (int na = 0; na < NWT; na++)
#pragma unroll
            for (int q = 0; q < 4; q++) acc[mi][na][q] = 0.f;

    const uint32_t smb = smem_u32(sm);

    auto g_load = [&](float4* av, float4* bv, int k0) {
#pragma unroll
        for (int i = 0; i < 2; i++)
            av[i] = *(const float4*)(A + (size_t)(m0 + arow[i]) * KD + k0 + acol[i]);
#pragma unroll
        for (int i = 0; i < NWT; i++)
            bv[i] = *(const float4*)(Bw + (size_t)(n0 + brow[i]) * KD + k0 + bcol[i]);
    };
    auto s_store = [&](int s, const float4* av, const float4* bv) {
        char* st   = sm + s * FSTAGE;
        char* a_hi = st;
        char* a_lo = st + FAB;
        char* b_hi = st + 2 * FAB;
        char* b_lo = st + 2 * FAB + FBB;
#pragma unroll
        for (int i = 0; i < 2; i++) {
            uint2 hi, lo;
            split4(av[i], hi, lo);
            const int off = (arow[i] * FSA + acol[i]) * 2;
            *(uint2*)(a_hi + off) = hi;
            *(uint2*)(a_lo + off) = lo;
        }
#pragma unroll
        for (int i = 0; i < NWT; i++) {
            uint2 hi, lo;
            split4(bv[i], hi, lo);
            const int off = (brow[i] * FSB + bcol[i]) * 2;
            *(uint2*)(b_hi + off) = hi;
            *(uint2*)(b_lo + off) = lo;
        }
    };

    uint32_t a_off[2][2], b_off[NJ][2];
#pragma unroll
    for (int ks = 0; ks < 2; ks++) {
#pragma unroll
        for (int mi = 0; mi < 2; mi++) {
            int row = wm * 32 + mi * 16 + (lane & 15);
            int col = ks * 16 + ((lane >> 4) << 3);
            a_off[mi][ks] = (uint32_t)(row * FSA + col) * 2;
        }
#pragma unroll
        for (int j = 0; j < NJ; j++) {
            int row = wn * (NWT * 8) + j * 16 + (((lane >> 4) & 1) << 3) + (lane & 7);
            int col = ks * 16 + (((lane >> 3) & 1) << 3);
            b_off[j][ks] = (uint32_t)(row * FSB + col) * 2;
        }
    }

    auto compute = [&](int s) {
        const uint32_t s_ahi = smb + s * FSTAGE;
        const uint32_t s_alo = s_ahi + FAB;
        const uint32_t s_bhi = s_ahi + 2 * FAB;
        const uint32_t s_blo = s_bhi + FBB;
#pragma unroll
        for (int ks = 0; ks < 2; ks++) {
            uint32_t ahi[2][4], alo[2][4], bhi[NJ][4], blo[NJ][4];
#pragma unroll
            for (int mi = 0; mi < 2; mi++) {
                ldm_x4(ahi[mi], s_ahi + a_off[mi][ks]);
                ldm_x4(alo[mi], s_alo + a_off[mi][ks]);
            }
#pragma unroll
            for (int j = 0; j < NJ; j++) {
                ldm_x4(bhi[j], s_bhi + b_off[j][ks]);
                ldm_x4(blo[j], s_blo + b_off[j][ks]);
            }
#pragma unroll
            for (int mi = 0; mi < 2; mi++)
#pragma unroll
                for (int na = 0; na < NWT; na++) {
                    const uint32_t* bh = &bhi[na >> 1][(na & 1) * 2];
                    const uint32_t* bl = &blo[na >> 1][(na & 1) * 2];
                    mma16816(acc[mi][na], ahi[mi], bh);
                    mma16816(acc[mi][na], ahi[mi], bl);
                    mma16816(acc[mi][na], alo[mi], bh);
                }
        }
    };

    float4 a0[2], b0[NWT], a1[2], b1[NWT];
    g_load(a0, b0, 0);
    s_store(0, a0, b0);
    g_load(a1, b1, FBK);
    __syncthreads();
#pragma unroll 1
    for (int kc = 0; kc < ITERS; kc += 2) {
        if (kc + 2 < ITERS) g_load(a0, b0, (kc + 2) * FBK);
        compute(0);
        if (kc + 1 < ITERS) s_store(1, a1, b1);
        __syncthreads();
        if (kc + 1 < ITERS) {
            if (kc + 3 < ITERS) g_load(a1, b1, (kc + 3) * FBK);
            compute(1);
            if (kc + 2 < ITERS) s_store(0, a0, b0);
            __syncthreads();
        }
    }

    const int g  = lane >> 2;
    const int tg = lane & 3;
#pragma unroll
    for (int mi = 0; mi < 2; mi++) {
#pragma unroll
        for (int na = 0; na < NWT; na++) {
            const int col = n0 + wn * (NWT * 8) + na * 8 + tg * 2;
            const int r0 = m0 + wm * 32 + mi * 16 + g;
            float2 v0, v1;
            v0.x = acc[mi][na][0];
            v0.y = acc[mi][na][1];
            v1.x = acc[mi][na][2];
            v1.y = acc[mi][na][3];
            *(float2*)&C[(size_t)r0 * Nld + col]       = v0;
            *(float2*)&C[(size_t)(r0 + 8) * Nld + col] = v1;
        }
    }
}

#define STAGE_OF(NWT) (2 * FAB + 2 * ((NWT) * 32 * FSB * 2))
#define SMEM_OF(NWT)  (2 * STAGE_OF(NWT))

// ---------------- embedding gather -----------------------------------------
__global__ void prep_kernel(const int* __restrict__ word,
                            const float* __restrict__ emb)
{
    const int b = blockIdx.x;
    const int t = threadIdx.x;                 // 512
    const float v = emb[(size_t)word[b] * 512 + t];
    g_x[b * RNNIN + t] = v;
    g_comb[b * COMB + RNNIN + t] = v;
}

// ------- flash attention, DOUBLE-BUFFERED tile: enc read once ---------------
#define ACH 8
#define ATT_SMEM ((ENCD + 2 * ACH * ENCD + S_ + 8) * 4)

__global__ void __launch_bounds__(256) attn_flash(
    const float* __restrict__ enc, const int* __restrict__ src,
    float* __restrict__ out_scores)
{
    extern __shared__ float asm_[];
    float* qs   = asm_;                       // [1024]
    float* tl   = asm_ + ENCD;                // [2][8][1024]
    float* satt = asm_ + ENCD + 2 * ACH * ENCD;  // [200]
    __shared__ float attc[2][ACH];

    const int b = blockIdx.x;
    const int tid = threadIdx.x;
    const int warp = tid >> 5, lane = tid & 31;

    for (int d = tid; d < ENCD; d += 256) qs[d] = g_q[b * ENCD + d];
    __syncthreads();

    const float* encb = enc + (size_t)b * S_ * ENCD;

    float4 r[8];
    auto ldchunk = [&](int s0) {
        const float* e = encb + (size_t)(s0 + warp) * ENCD;
#pragma unroll
        for (int i = 0; i < 8; i++)
            r[i] = *(const float4*)(e + (lane + 32 * i) * 4);
    };
    auto store_dot = [&](int buf, int s0) {
        float* trow = tl + (buf * ACH + warp) * ENCD;
        float acc = 0.f;
#pragma unroll
        for (int i = 0; i < 8; i++) {
            const int d4 = (lane + 32 * i) * 4;
            *(float4*)(trow + d4) = r[i];
            acc += r[i].x * qs[d4] + r[i].y * qs[d4 + 1]
                 + r[i].z * qs[d4 + 2] + r[i].w * qs[d4 + 3];
        }
#pragma unroll
        for (int o = 16; o; o >>= 1) acc += __shfl_xor_sync(~0u, acc, o);
        if (lane == 0) {
            const int s = s0 + warp;
            const float a = (src[b * S_ + s] == 0) ? -1000000.0f : acc;
            attc[buf][warp] = a;
            satt[s] = a;
        }
    };

    float m = -INFINITY, l = 0.f;
    float c0 = 0.f, c1 = 0.f, c2 = 0.f, c3 = 0.f;

    ldchunk(0);
    store_dot(0, 0);
    __syncthreads();

    constexpr int NCH = S_ / ACH;             // 25
#pragma unroll 1
    for (int c = 0; c < NCH; ++c) {
        const int cur = c & 1;
        if (c + 1 < NCH) ldchunk((c + 1) * ACH);
        const float* tb = tl + cur * ACH * ENCD;
#pragma unroll
        for (int rr = 0; rr < ACH; rr++) {
            const float a = attc[cur][rr];
            const float mn = fmaxf(m, a);
            const float scale = __expf(m - mn);
            const float f = __expf(a - mn);
            const float* tr = tb + rr * ENCD;
            c0 = c0 * scale + f * tr[tid];
            c1 = c1 * scale + f * tr[tid + 256];
            c2 = c2 * scale + f * tr[tid + 512];
            c3 = c3 * scale + f * tr[tid + 768];
            l = l * scale + f;
            m = mn;
        }
        if (c + 1 < NCH) store_dot(cur ^ 1, (c + 1) * ACH);
        __syncthreads();
    }

    const float inv = 1.f / l;
    c0 *= inv; c1 *= inv; c2 *= inv; c3 *= inv;
    const int d = tid;
    g_x[b * RNNIN + 512 + d]       = c0;   g_comb[b * COMB + 512 + d]       = c0;
    g_x[b * RNNIN + 512 + d + 256] = c1;   g_comb[b * COMB + 512 + d + 256] = c1;
    g_x[b * RNNIN + 512 + d + 512] = c2;   g_comb[b * COMB + 512 + d + 512] = c2;
    g_x[b * RNNIN + 512 + d + 768] = c3;   g_comb[b * COMB + 512 + d + 768] = c3;

    if (tid < S_) out_scores[b * S_ + tid] = __expf(satt[tid] - m) * inv;
}

// ---------------- GRU gates -------------------------------------------------
__global__ void gru_kernel(const float* __restrict__ h_prev,
                           const float* __restrict__ b_ih,
                           const float* __restrict__ b_hh,
                           float* __restrict__ out_hidden)
{
    const int b = blockIdx.x;
    const int t = threadIdx.x;                 // 512
    const float ir  = g_gi[b * G3 + t]         + b_ih[t];
    const float iz  = g_gi[b * G3 + 512 + t]   + b_ih[512 + t];
    const float in_ = g_gi[b * G3 + 1024 + t]  + b_ih[1024 + t];
    const float hr  = g_gh[b * G3 + t]         + b_hh[t];
    const float hz  = g_gh[b * G3 + 512 + t]   + b_hh[512 + t];
    const float hn  = g_gh[b * G3 + 1024 + t]  + b_hh[1024 + t];
    const float r = 1.f / (1.f + __expf(-(ir + hr)));
    const float z = 1.f / (1.f + __expf(-(iz + hz)));
    const float n = tanhf(in_ + r * hn);
    const float h = (1.f - z) * n + z * h_prev[b * DECH + t];
    out_hidden[b * DECH + t] = h;
    g_comb[b * COMB + t] = h;
}

// ---- softmax over V (online) + inline prob_gen + scaling + fused scatter ----
__global__ void __launch_bounds__(1024) softmax_kernel(
    float* __restrict__ out, const int* __restrict__ src,
    const float* __restrict__ scores,
    const float* __restrict__ ptr_w, const float* __restrict__ ptr_b)
{
    const int b = blockIdx.x;
    const int tid = threadIdx.x;
    const float* lg = g_logits + (size_t)b * V_;
    __shared__ float redm[32], reds[32];
    __shared__ float sh_pg;

    // inline prob_gen: dot(comb[b], ptr_w) over 2048 elems
    {
        float accp = 0.f;
        accp = fmaf(g_comb[b * COMB + tid],        __ldg(&ptr_w[tid]),        accp);
        accp = fmaf(g_comb[b * COMB + tid + 1024], __ldg(&ptr_w[tid + 1024]), accp);
#pragma unroll
        for (int o = 16; o; o >>= 1) accp += __shfl_xor_sync(~0u, accp, o);
        if ((tid & 31) == 0) redm[tid >> 5] = accp;
        __syncthreads();
        if (tid < 32) {
            float t = redm[tid];
#pragma unroll
            for (int o = 16; o; o >>= 1) t += __shfl_xor_sync(~0u, t, o);
            if (tid == 0) sh_pg = 1.f / (1.f + __expf(-(t + __ldg(&ptr_b[0]))));
        }
        __syncthreads();
    }

    float m = -INFINITY, s = 0.f;
    for (int v = tid; v < V_; v += 1024) {
        const float x = lg[v];
        const float mo = m;
        m = fmaxf(m, x);
        s = s * __expf(mo - m) + __expf(x - m);
    }
#pragma unroll
    for (int o = 16; o; o >>= 1) {
        const float m2 = __shfl_xor_sync(~0u, m, o);
        const float s2 = __shfl_xor_sync(~0u, s, o);
        const float mn = fmaxf(m, m2);
        s = s * __expf(m - mn) + s2 * __expf(m2 - mn);
        m = mn;
    }
    if ((tid & 31) == 0) { redm[tid >> 5] = m; reds[tid >> 5] = s; }
    __syncthreads();
    if (tid < 32) {
        float mm = redm[tid], ss = reds[tid];
#pragma unroll
        for (int o = 16; o; o >>= 1) {
            const float m2 = __shfl_xor_sync(~0u, mm, o);
            const float s2 = __shfl_xor_sync(~0u, ss, o);
            const float mn = fmaxf(mm, m2);
            ss = ss * __expf(mm - mn) + s2 * __expf(m2 - mn);
            mm = mn;
        }
        if (tid == 0) { redm[0] = mm; reds[0] = ss; }
    }
    __syncthreads();
    m = redm[0];
    const float pg = sh_pg;
    const float scale = pg / reds[0];
    for (int v = tid; v < V_; v += 1024)
        out[(size_t)b * V_ + v] = __expf(lg[v] - m) * scale;
    __syncthreads();
    if (tid < S_) {
        const int idx = src[b * S_ + tid];
        atomicAdd(&out[(size_t)b * V_ + idx], (1.f - pg) * scores[b * S_ + tid]);
    }
}

// ---------------- launch -----------------------------------------------------
extern "C" void kernel_launch(void* const* d_in, const int* in_sizes, int n_in,
                              void* d_out, int out_size)
{
    const int*   word    = (const int*)  d_in[0];
    const float* dh      = (const float*)d_in[1];
    const float* enc     = (const float*)d_in[2];
    const int*   src     = (const int*)  d_in[3];
    const float* emb     = (const float*)d_in[4];
    const float* W_attn  = (const float*)d_in[5];
    const float* w_ih    = (const float*)d_in[6];
    const float* w_hh    = (const float*)d_in[7];
    const float* b_ih    = (const float*)d_in[8];
    const float* b_hh    = (const float*)d_in[9];
    const float* fc_w    = (const float*)d_in[10];
    const float* fc_b    = (const float*)d_in[11];
    const float* ptr_w   = (const float*)d_in[12];
    const float* ptr_b   = (const float*)d_in[13];

    float* out        = (float*)d_out;
    float* out_probs  = out;                                 // (B,1,V)
    float* out_hidden = out + (size_t)B_ * V_;               // (B,DECH)
    float* out_scores = out_hidden + (size_t)B_ * DECH;      // (B,1,S)

    float *pq, *px, *pcomb, *pgi, *pgh, *plog;
    cudaGetSymbolAddress((void**)&pq,    g_q);
    cudaGetSymbolAddress((void**)&px,    g_x);
    cudaGetSymbolAddress((void**)&pcomb, g_comb);
    cudaGetSymbolAddress((void**)&pgi,   g_gi);
    cudaGetSymbolAddress((void**)&pgh,   g_gh);
    cudaGetSymbolAddress((void**)&plog,  g_logits);

    static bool attr_set = false;
    if (!attr_set) {
        cudaFuncSetAttribute((void*)gemm_mma<2048, 4, 1>,
            cudaFuncAttributeMaxDynamicSharedMemorySize, SMEM_OF(4));
        cudaFuncSetAttribute((void*)gemm_mma<1536, 2, 2>,
            cudaFuncAttributeMaxDynamicSharedMemorySize, SMEM_OF(2));
        cudaFuncSetAttribute((void*)qgh_gemm,
            cudaFuncAttributeMaxDynamicSharedMemorySize, SMEM_OF(2));
        cudaFuncSetAttribute((void*)attn_flash,
            cudaFuncAttributeMaxDynamicSharedMemorySize, ATT_SMEM);
        attr_set = true;
    }

    // 1) embedding gather into x and comb
    prep_kernel<<<B_, 512>>>(word, emb);
    // 2) q = dh @ W_attn^T AND gh = dh @ w_hh^T in ONE launch
    qgh_gemm<<<dim3(B_/FBM, (ENCD + G3)/64), 256, SMEM_OF(2)>>>(
        dh, W_attn, w_hh, pq, pgh);
    // 3) flash attention (double-buffered tile): scores + context
    attn_flash<<<B_, 256, ATT_SMEM>>>(enc, src, out_scores);
    // 4) gi = x @ w_ih^T
    gemm_mma<1536, 2, 2><<<dim3(B_/FBM, G3/64), 256, SMEM_OF(2)>>>(
        px, w_ih, nullptr, pgi, G3);
    // 5) GRU gates -> hidden
    gru_kernel<<<B_, 512>>>(dh, b_ih, b_hh, out_hidden);
    // 6) logits = comb @ fc_w^T + fc_b (R8/R14 proven config: NWT=4, DEPTH=1)
    gemm_mma<2048, 4, 1><<<dim3(B_/FBM, V_/128), 256, SMEM_OF(4)>>>(
        pcomb, fc_w, fc_b, plog, V_);
    // 7) out = prob_gen * softmax(logits) + inline prob_gen + fused scatter
    softmax_kernel<<<B_, 1024>>>(out_probs, src, out_scores, ptr_w, ptr_b);
}